// round 7
// baseline (speedup 1.0000x reference)
#include <cuda_runtime.h>
#include <math.h>

#define B_   16
#define C_   384
#define CH_  64
#define CF_  193
#define KP_  256     // padded K dim for irfft tables
#define HW_  16384   // 128*128
#define POOLB (B_ * C_)   // 6144

__device__ float g_y0[B_ * C_];          // pooled means
__device__ float g_h [B_ * CH_];         // hidden relu
__device__ float g_ys[B_ * C_];          // sigmoid gate y
__device__ float g_rRe[B_ * CF_];        // spectral re
__device__ float g_rIm[B_ * CF_];        // spectral im
__device__ float g_W1c [CH_ * C_];       // W1 center taps   [j][n]
__device__ float g_W2cT[CH_ * C_];       // W2 center taps^T [j][c]
__device__ float g_dftSC[CF_ * C_];      // fwd DFT cos [k][n]
__device__ float g_dftSS[CF_ * C_];      // fwd DFT sin [k][n]
__device__ float g_dftIC[C_ * KP_];      // irfft cos*wgt [n][k], 0-padded k>=193
__device__ float g_dftIS[C_ * KP_];      // irfft sin*wgt [n][k], 0-padded

// ---------------------------------------------------------------------------
// Kernel 1: global average pool (blocks 0..6143) + 12 weight-compaction
// side blocks (needed by k_h / k_gate next).
// ---------------------------------------------------------------------------
__global__ __launch_bounds__(256) void pool_kernel(
    const float* __restrict__ x,
    const float* __restrict__ W1, const float* __restrict__ W2)
{
    const int bid = blockIdx.x;
    const int t   = threadIdx.x;

    if (bid >= POOLB) {
        const int s = bid - POOLB;                      // 0..11
        if (s < 6) {                                    // W1 center taps
            for (int e = s * 4096 + t; e < (s + 1) * 4096; e += 256) {
                int j = e / C_, n = e - j * C_;
                g_W1c[e] = W1[j * (C_ * 9) + n * 9 + 4];
            }
        } else {                                        // W2 center taps ^T
            for (int e = (s - 6) * 4096 + t; e < (s - 5) * 4096; e += 256) {
                int j = e / C_, c = e - j * C_;
                g_W2cT[e] = W2[c * (CH_ * 9) + j * 9 + 4];
            }
        }
        return;
    }

    const float4* __restrict__ p =
        reinterpret_cast<const float4*>(x + (size_t)bid * HW_);
    float s = 0.f;
#pragma unroll
    for (int i = 0; i < 16; ++i) {
        float4 v = __ldcs(p + t + 256 * i);
        s += (v.x + v.y) + (v.z + v.w);
    }
#pragma unroll
    for (int o = 16; o > 0; o >>= 1) s += __shfl_down_sync(0xffffffffu, s, o);
    __shared__ float ws[8];
    if ((t & 31) == 0) ws[t >> 5] = s;
    __syncthreads();
    if (t < 8) {
        s = ws[t];
#pragma unroll
        for (int o = 4; o > 0; o >>= 1) s += __shfl_down_sync(0xffu, s, o);
        if (t == 0) g_y0[bid] = s * (1.f / (float)HW_);
    }
}

// ---------------------------------------------------------------------------
// Kernel 2: h[b,j] (blocks 0..127, warp per (b,j), float4) + 84 side blocks
// building the DFT tables (needed by k_spec / k_irfft later).
// ---------------------------------------------------------------------------
__global__ __launch_bounds__(256) void k_h(const float* __restrict__ b1)
{
    const int bid = blockIdx.x;
    const int t   = threadIdx.x;

    if (bid >= 128) {
        const int s = bid - 128;                        // 0..83
        __shared__ float cT[C_], sT[C_];
        for (int m = t; m < C_; m += 256) {
            float sv, cv;
            sincosf((float)m * (6.283185307179586f / (float)C_), &sv, &cv);
            cT[m] = cv;
            sT[m] = sv;
        }
        __syncthreads();
        if (s < 42) {                                   // forward [k][n]
            const int NT = CF_ * C_;
            const int lo = (NT * s) / 42, hi = (NT * (s + 1)) / 42;
            for (int e = lo + t; e < hi; e += 256) {
                int k = e / C_, n = e - k * C_;
                int m = (k * n) % C_;
                g_dftSC[e] = cT[m];
                g_dftSS[e] = sT[m];
            }
        } else {                                        // inverse [n][KP], wgt folded
            const int g = s - 42;                       // 0..41
            const int NT = C_ * KP_;
            const int lo = (NT * g) / 42, hi = (NT * (g + 1)) / 42;
            for (int e = lo + t; e < hi; e += 256) {
                int n = e / KP_, k = e - n * KP_;
                if (k >= CF_) { g_dftIC[e] = 0.f; g_dftIS[e] = 0.f; continue; }
                int m = (k * n) % C_;
                float wgt = (k >= 1 && k <= 191) ? 2.f : 1.f;
                g_dftIC[e] = wgt * cT[m];
                g_dftIS[e] = wgt * sT[m];
            }
        }
        return;
    }

    const int wid  = bid * 8 + (t >> 5);                // 0..1023
    const int lane = t & 31;
    const int b = wid >> 6;
    const int j = wid & 63;
    const float4* __restrict__ y0 = reinterpret_cast<const float4*>(g_y0 + b * C_);
    const float4* __restrict__ wr = reinterpret_cast<const float4*>(g_W1c + j * C_);
    float acc = 0.f;
#pragma unroll
    for (int i = 0; i < 3; ++i) {
        float4 a = y0[lane * 3 + i];
        float4 w = wr[lane * 3 + i];
        acc += a.x * w.x + a.y * w.y + a.z * w.z + a.w * w.w;
    }
#pragma unroll
    for (int o = 16; o > 0; o >>= 1) acc += __shfl_down_sync(0xffffffffu, acc, o);
    if (lane == 0) g_h[wid] = fmaxf(acc + b1[j], 0.f);
}

// ---------------------------------------------------------------------------
// Kernel 3: y[b,c] = sigmoid(h[b,:] . W2cT[:,c] + b2[c]). 24 blocks x 256.
// ---------------------------------------------------------------------------
__global__ __launch_bounds__(256) void k_gate(const float* __restrict__ b2)
{
    const int bc = blockIdx.x * 256 + threadIdx.x;
    const int b = bc / C_;
    const int c = bc - b * C_;
    const float* __restrict__ h = g_h + b * CH_;
    float acc = b2[c];
#pragma unroll
    for (int j = 0; j < CH_; ++j)
        acc += h[j] * g_W2cT[j * C_ + c];
    g_ys[bc] = 1.f / (1.f + expf(-acc));
}

// ---------------------------------------------------------------------------
// Kernel 4: spectral bins. Block = (b, 8 bins), grid 400. Warp per k.
// float4 everywhere: lane owns n-chunk [lane*12, lane*12+12).
// ---------------------------------------------------------------------------
__global__ __launch_bounds__(256) void k_spec(
    const float* __restrict__ Ws1, const float* __restrict__ bs1,
    const float* __restrict__ Ws2, const float* __restrict__ bs2)
{
    const int b    = blockIdx.x / 25;
    const int kg   = blockIdx.x - b * 25;
    const int t    = threadIdx.x;
    const int lane = t & 31;

    __shared__ float ys[C_];
    for (int m = t; m < C_; m += 256) ys[m] = g_ys[b * C_ + m];
    __syncthreads();

    const int k = kg * 8 + (t >> 5);
    if (k >= CF_) return;

    const float4* __restrict__ tc = reinterpret_cast<const float4*>(g_dftSC + k * C_);
    const float4* __restrict__ ts = reinterpret_cast<const float4*>(g_dftSS + k * C_);
    const float4* __restrict__ w1 = reinterpret_cast<const float4*>(Ws1 + k * C_);
    const float4* __restrict__ w2 = reinterpret_cast<const float4*>(Ws2 + k * C_);
    const float4* __restrict__ yv4 = reinterpret_cast<const float4*>(ys);

    float re = 0.f, im = 0.f, a1 = 0.f, a2 = 0.f;
#pragma unroll
    for (int i = 0; i < 3; ++i) {
        const int q = lane * 3 + i;
        float4 y = yv4[q];
        float4 c = tc[q], s = ts[q], u = w1[q], v = w2[q];
        re += y.x * c.x + y.y * c.y + y.z * c.z + y.w * c.w;
        im -= y.x * s.x + y.y * s.y + y.z * s.z + y.w * s.w;
        a1 += y.x * u.x + y.y * u.y + y.z * u.z + y.w * u.w;
        a2 += y.x * v.x + y.y * v.y + y.z * v.z + y.w * v.w;
    }
#pragma unroll
    for (int o = 16; o > 0; o >>= 1) {
        re += __shfl_down_sync(0xffffffffu, re, o);
        im += __shfl_down_sync(0xffffffffu, im, o);
        a1 += __shfl_down_sync(0xffffffffu, a1, o);
        a2 += __shfl_down_sync(0xffffffffu, a2, o);
    }
    if (lane == 0) {
        float s1  = fmaxf(a1 + bs1[k], 0.f);
        float s2  = fmaxf(a2 + bs2[k], 0.f);
        float amp = sqrtf(re * re + im * im) * s1;
        float ph  = atan2f(im, re) * s2;
        float sp, cp;
        sincosf(ph, &sp, &cp);
        g_rRe[b * CF_ + k] = amp * cp;
        g_rIm[b * CF_ + k] = amp * sp;
    }
}

// ---------------------------------------------------------------------------
// Kernel 5: irfft + gate. Block = (b, 8 outputs), grid 768. Warp per n.
// Lane owns 8 consecutive k (2 x float4 per stream); K padded to 256 with
// zero-folded weights so no bounds checks.
// ---------------------------------------------------------------------------
__global__ __launch_bounds__(256) void k_irfft(float* __restrict__ out)
{
    const int b  = blockIdx.x / 48;
    const int ng = blockIdx.x - b * 48;
    const int t  = threadIdx.x;
    const int lane = t & 31;

    __shared__ float sRe[KP_], sIm[KP_];
    for (int m = t; m < KP_; m += 256) {
        sRe[m] = (m < CF_) ? g_rRe[b * CF_ + m] : 0.f;
        sIm[m] = (m < CF_) ? g_rIm[b * CF_ + m] : 0.f;
    }
    __syncthreads();

    const int n = ng * 8 + (t >> 5);
    const float4* __restrict__ tc = reinterpret_cast<const float4*>(g_dftIC + n * KP_);
    const float4* __restrict__ ts = reinterpret_cast<const float4*>(g_dftIS + n * KP_);
    const float4* __restrict__ re4 = reinterpret_cast<const float4*>(sRe);
    const float4* __restrict__ im4 = reinterpret_cast<const float4*>(sIm);

    float acc = 0.f;
#pragma unroll
    for (int i = 0; i < 2; ++i) {
        const int q = lane * 2 + i;
        float4 c = tc[q], s = ts[q], r = re4[q], m = im4[q];
        acc += c.x * r.x + c.y * r.y + c.z * r.z + c.w * r.w;
        acc -= s.x * m.x + s.y * m.y + s.z * m.z + s.w * m.w;
    }
#pragma unroll
    for (int o = 16; o > 0; o >>= 1) acc += __shfl_down_sync(0xffffffffu, acc, o);
    if (lane == 0) {
        float xr = acc * (1.f / (float)C_);
        out[b * C_ + n] = xr * g_ys[b * C_ + n];
    }
}

// ---------------------------------------------------------------------------
extern "C" void kernel_launch(void* const* d_in, const int* in_sizes, int n_in,
                              void* d_out, int out_size) {
    const float* x   = (const float*)d_in[0];
    const float* W1  = (const float*)d_in[1];
    const float* b1  = (const float*)d_in[2];
    const float* W2  = (const float*)d_in[3];
    const float* b2  = (const float*)d_in[4];
    const float* Ws1 = (const float*)d_in[5];
    const float* bs1 = (const float*)d_in[6];
    const float* Ws2 = (const float*)d_in[7];
    const float* bs2 = (const float*)d_in[8];
    float* out = (float*)d_out;

    pool_kernel<<<POOLB + 12, 256>>>(x, W1, W2);
    k_h<<<128 + 84, 256>>>(b1);
    k_gate<<<B_ * C_ / 256, 256>>>(b2);
    k_spec<<<B_ * 25, 256>>>(Ws1, bs1, Ws2, bs2);
    k_irfft<<<B_ * 48, 256>>>(out);
}